// round 2
// baseline (speedup 1.0000x reference)
#include <cuda_runtime.h>
#include <math.h>

#define SD     16
#define IDIM   64
#define ODIM   64
#define NBATCH 32
#define SEQLEN 8192
#define LCH    64
#define NCH    (SEQLEN/LCH)
#define DTVAL  1.0f
#define FULLMASK 0xffffffffu

__device__ __align__(16) float g_Ad[SD*SD];
__device__ __align__(16) float g_AdL[SD*SD];
__device__ __align__(16) float g_Bd[SD*IDIM];
__device__ __align__(16) float g_H[NBATCH*SEQLEN*SD];
__device__ __align__(16) float g_hprev[NBATCH*NCH*SD];

// ---------------- K0: discretization (1 block, 256 threads) ----------------
__global__ void k0_setup(const float* __restrict__ ll, const float* __restrict__ p,
                         const float* __restrict__ q,  const float* __restrict__ B,
                         const float* __restrict__ P) {
    __shared__ float core[SD*SD], tmp[SD*SD], Ac[SD*SD];
    __shared__ float aug[SD][96];
    __shared__ float fvec[SD];
    __shared__ float Sp[2][SD*SD];
    __shared__ int   pivs;
    int t = threadIdx.x;

    if (t < SD*SD) {
        int i = t >> 4, j = t & 15;
        float v = p[i] * q[j];
        if (i == j) v -= expf(ll[i]);
        core[t] = v;
    }
    __syncthreads();
    if (t < SD*SD) {
        int i = t >> 4, j = t & 15;
        float s = 0.f;
        for (int k = 0; k < SD; k++) s += P[i*SD+k] * core[k*SD+j];
        tmp[t] = s;
    }
    __syncthreads();
    if (t < SD*SD) {
        int i = t >> 4, j = t & 15;
        float s = 0.f;
        for (int k = 0; k < SD; k++) s += tmp[i*SD+k] * P[j*SD+k];
        Ac[t] = s;
    }
    __syncthreads();
    for (int f = t; f < SD*96; f += 256) {
        int r = f / 96, c = f % 96;
        float v;
        if (c < 16)      v = (r == c      ? 1.f : 0.f) - 0.5f*DTVAL*Ac[r*SD+c];
        else if (c < 32) v = (r == (c-16) ? 1.f : 0.f) + 0.5f*DTVAL*Ac[r*SD+(c-16)];
        else             v = DTVAL * B[r*IDIM + (c-32)];
        aug[r][c] = v;
    }
    __syncthreads();
    for (int col = 0; col < SD; col++) {
        if (t == 0) {
            int best = col; float bv = fabsf(aug[col][col]);
            for (int r = col+1; r < SD; r++) {
                float v = fabsf(aug[r][col]);
                if (v > bv) { bv = v; best = r; }
            }
            pivs = best;
        }
        __syncthreads();
        int pr = pivs;
        if (pr != col && t < 96) { float a = aug[col][t]; aug[col][t] = aug[pr][t]; aug[pr][t] = a; }
        __syncthreads();
        float pv = aug[col][col];
        if (t < SD) fvec[t] = aug[t][col];
        __syncthreads();
        if (t < 96) aug[col][t] *= (1.f / pv);
        __syncthreads();
        for (int f = t; f < SD*96; f += 256) {
            int r = f / 96, c = f % 96;
            if (r != col) aug[r][c] = fmaf(-fvec[r], aug[col][c], aug[r][c]);
        }
        __syncthreads();
    }
    if (t < SD*SD) { int r = t >> 4, c = t & 15; float v = aug[r][16+c]; g_Ad[t] = v; Sp[0][t] = v; }
    for (int f = t; f < SD*IDIM; f += 256) { int r = f / IDIM, c = f % IDIM; g_Bd[f] = aug[r][32+c]; }
    __syncthreads();
    int cur = 0;
    for (int it = 0; it < 6; it++) {
        if (t < SD*SD) {
            int i = t >> 4, j = t & 15;
            float s = 0.f;
            for (int k = 0; k < SD; k++) s += Sp[cur][i*SD+k] * Sp[cur][k*SD+j];
            Sp[cur^1][t] = s;
        }
        __syncthreads();
        cur ^= 1;
    }
    if (t < SD*SD) g_AdL[t] = Sp[cur][t];
}

// ---------------- K1: local chunk scan (warp per (batch, chunk)) ----------------
__global__ void __launch_bounds__(256) k1_local(const float* __restrict__ x) {
    __shared__ __align__(16) float xs[8][16*64];
    __shared__ __align__(16) float hs[8][16*16];
    int warp = threadIdx.x >> 5, lane = threadIdx.x & 31;
    int wid = blockIdx.x * 8 + warp;
    int b = wid >> 7, c = wid & (NCH - 1);
    int n = lane & 15, half = lane >> 4;

    float Breg[32], Areg[16];
    {
        const float4* bp = (const float4*)(g_Bd + n*IDIM + half*32);
#pragma unroll
        for (int i = 0; i < 8; i++) { float4 v = bp[i]; Breg[4*i]=v.x; Breg[4*i+1]=v.y; Breg[4*i+2]=v.z; Breg[4*i+3]=v.w; }
        const float4* ap = (const float4*)(g_Ad + n*SD);
#pragma unroll
        for (int i = 0; i < 4; i++) { float4 v = ap[i]; Areg[4*i]=v.x; Areg[4*i+1]=v.y; Areg[4*i+2]=v.z; Areg[4*i+3]=v.w; }
    }
    const float4* gx = (const float4*)(x + ((size_t)b*SEQLEN + (size_t)c*LCH)*IDIM);
    float* gH = g_H + ((size_t)b*SEQLEN + (size_t)c*LCH)*SD;
    float* xw = xs[warp];
    float* hw = hs[warp];
    float h = 0.f;

    for (int tile = 0; tile < LCH/16; tile++) {
#pragma unroll
        for (int i = 0; i < 8; i++)
            ((float4*)xw)[lane + 32*i] = gx[tile*256 + lane + 32*i];
        __syncwarp();
#pragma unroll
        for (int tt = 0; tt < 16; tt++) {
            const float* xp = xw + tt*64 + half*32;
            float ua0=0.f, ua1=0.f, ua2=0.f, ua3=0.f;
#pragma unroll
            for (int k4 = 0; k4 < 8; k4++) {
                float4 v = *(const float4*)(xp + 4*k4);
                ua0 = fmaf(Breg[4*k4+0], v.x, ua0);
                ua1 = fmaf(Breg[4*k4+1], v.y, ua1);
                ua2 = fmaf(Breg[4*k4+2], v.z, ua2);
                ua3 = fmaf(Breg[4*k4+3], v.w, ua3);
            }
            float u = (ua0 + ua1) + (ua2 + ua3);
            u += __shfl_xor_sync(FULLMASK, u, 16);
            float h0 = u, h1 = 0.f;
#pragma unroll
            for (int m = 0; m < 16; m += 2) {
                h0 = fmaf(Areg[m],   __shfl_sync(FULLMASK, h, m),   h0);
                h1 = fmaf(Areg[m+1], __shfl_sync(FULLMASK, h, m+1), h1);
            }
            h = h0 + h1;
            if (half == 0) hw[tt*16 + n] = h;
        }
        __syncwarp();
        ((float4*)gH)[tile*64 + lane]      = ((float4*)hw)[lane];
        ((float4*)gH)[tile*64 + 32 + lane] = ((float4*)hw)[lane + 32];
        __syncwarp();
    }
}

// ---------------- K2: boundary scan across chunks (block of 32 per batch) ----------------
__global__ void k2_scan() {
    __shared__ float ss[NCH*SD];
    int b = blockIdx.x;
    int lane = threadIdx.x;
    int n = lane & 15;
    for (int f = lane; f < NCH*SD; f += 32) {
        int c = f >> 4, nn = f & 15;
        ss[f] = g_H[((size_t)b*SEQLEN + (size_t)c*LCH + (LCH-1))*SD + nn];
    }
    __syncwarp();
    float AL[16];
    {
        const float4* ap = (const float4*)(g_AdL + n*SD);
#pragma unroll
        for (int i = 0; i < 4; i++) { float4 v = ap[i]; AL[4*i]=v.x; AL[4*i+1]=v.y; AL[4*i+2]=v.z; AL[4*i+3]=v.w; }
    }
    float h = 0.f;
    for (int c = 0; c < NCH; c++) {
        if (lane < 16) g_hprev[((size_t)b*NCH + c)*SD + n] = h;
        float h0 = ss[c*SD + n], h1 = 0.f;
#pragma unroll
        for (int m = 0; m < 16; m += 2) {
            h0 = fmaf(AL[m],   __shfl_sync(FULLMASK, h, m),   h0);
            h1 = fmaf(AL[m+1], __shfl_sync(FULLMASK, h, m+1), h1);
        }
        h = h0 + h1;
    }
}

// ---------------- K2.5: correct local scans to global states (in place) ----------------
__global__ void __launch_bounds__(256) k25_fix() {
    __shared__ __align__(16) float ls[8][16*16];
    int warp = threadIdx.x >> 5, lane = threadIdx.x & 31;
    int wid = blockIdx.x * 8 + warp;
    int b = wid >> 7, c = wid & (NCH - 1);
    int n = lane & 15;

    float Areg[16];
    {
        const float4* ap = (const float4*)(g_Ad + n*SD);
#pragma unroll
        for (int i = 0; i < 4; i++) { float4 v = ap[i]; Areg[4*i]=v.x; Areg[4*i+1]=v.y; Areg[4*i+2]=v.z; Areg[4*i+3]=v.w; }
    }
    float z;
    {
        float zl = (lane < 16) ? g_hprev[((size_t)b*NCH + c)*SD + n] : 0.f;
        z = __shfl_sync(FULLMASK, zl, n);
    }
    float* gH = g_H + ((size_t)b*SEQLEN + (size_t)c*LCH)*SD;
    float* lw = ls[warp];
    for (int tile = 0; tile < LCH/16; tile++) {
        ((float4*)lw)[lane]      = ((float4*)gH)[tile*64 + lane];
        ((float4*)lw)[lane + 32] = ((float4*)gH)[tile*64 + 32 + lane];
        __syncwarp();
#pragma unroll
        for (int tt = 0; tt < 16; tt++) {
            float z0 = 0.f, z1 = 0.f;
#pragma unroll
            for (int m = 0; m < 16; m += 2) {
                z0 = fmaf(Areg[m],   __shfl_sync(FULLMASK, z, m),   z0);
                z1 = fmaf(Areg[m+1], __shfl_sync(FULLMASK, z, m+1), z1);
            }
            z = z0 + z1;
            if (lane < 16) lw[tt*16 + n] += z;
        }
        __syncwarp();
        ((float4*)gH)[tile*64 + lane]      = ((float4*)lw)[lane];
        ((float4*)gH)[tile*64 + 32 + lane] = ((float4*)lw)[lane + 32];
        __syncwarp();
    }
}

// ---------------- K3: Y = [X|H] @ [D|C]^T ----------------
__global__ void __launch_bounds__(256) k3_out(const float* __restrict__ x,
                                              const float* __restrict__ C,
                                              const float* __restrict__ D,
                                              float* __restrict__ y) {
    __shared__ __align__(16) float Zs[64*80];
    __shared__ __align__(16) float Ws[80*64];
    int tid = threadIdx.x;
    size_t row0 = (size_t)blockIdx.x * 64;
    const float4* gx = (const float4*)(x + row0*IDIM);
    const float4* gh = (const float4*)(g_H + row0*SD);

#pragma unroll
    for (int i = 0; i < 4; i++) {
        int f = tid + 256*i;
        int r = f >> 4, k0 = (f & 15) << 2;
        float4 v = gx[f];
        *(float4*)&Zs[r*80 + k0] = v;
    }
    {
        int r = tid >> 2, k0 = 64 + ((tid & 3) << 2);
        float4 v = gh[tid];
        *(float4*)&Zs[r*80 + k0] = v;
    }
#pragma unroll
    for (int i = 0; i < 20; i++) {
        int f = tid + 256*i;
        int k = f >> 6, o = f & 63;
        Ws[k*64 + o] = (k < 64) ? D[o*64 + k] : C[o*16 + (k - 64)];
    }
    __syncthreads();

    int tc = tid & 15, tr = tid >> 4;
    float acc[4][4];
#pragma unroll
    for (int r = 0; r < 4; r++)
#pragma unroll
        for (int cc = 0; cc < 4; cc++) acc[r][cc] = 0.f;

    const float* za = &Zs[(tr*4)*80];
#pragma unroll 8
    for (int k = 0; k < 80; k++) {
        float a[4];
#pragma unroll
        for (int r = 0; r < 4; r++) a[r] = za[r*80 + k];
        float4 bv = *(const float4*)&Ws[k*64 + tc*4];
#pragma unroll
        for (int r = 0; r < 4; r++) {
            acc[r][0] = fmaf(a[r], bv.x, acc[r][0]);
            acc[r][1] = fmaf(a[r], bv.y, acc[r][1]);
            acc[r][2] = fmaf(a[r], bv.z, acc[r][2]);
            acc[r][3] = fmaf(a[r], bv.w, acc[r][3]);
        }
    }
#pragma unroll
    for (int r = 0; r < 4; r++) {
        float4 ov = make_float4(acc[r][0], acc[r][1], acc[r][2], acc[r][3]);
        *(float4*)&y[(row0 + tr*4 + r)*ODIM + tc*4] = ov;
    }
}

extern "C" void kernel_launch(void* const* d_in, const int* in_sizes, int n_in,
                              void* d_out, int out_size) {
    const float* x  = (const float*)d_in[0];
    const float* ll = (const float*)d_in[1];
    const float* p  = (const float*)d_in[2];
    const float* q  = (const float*)d_in[3];
    const float* B  = (const float*)d_in[4];
    const float* C  = (const float*)d_in[5];
    const float* D  = (const float*)d_in[6];
    const float* P  = (const float*)d_in[7];
    float* y = (float*)d_out;

    k0_setup<<<1, 256>>>(ll, p, q, B, P);
    k1_local<<<(NBATCH*NCH)/8, 256>>>(x);
    k2_scan<<<NBATCH, 32>>>();
    k25_fix<<<(NBATCH*NCH)/8, 256>>>();
    k3_out<<<(NBATCH*SEQLEN)/64, 256>>>(x, C, D, y);
}

// round 4
// speedup vs baseline: 1.2709x; 1.2709x over previous
#include <cuda_runtime.h>
#include <math.h>

#define SD     16
#define IDIM   64
#define ODIM   64
#define NBATCH 32
#define SEQLEN 8192
#define LCH    64
#define NCH    (SEQLEN/LCH)
#define DTVAL  1.0f
#define FULLMASK 0xffffffffu

__device__ __align__(16) float g_Ad[SD*SD];
__device__ __align__(16) float g_AdL[SD*SD];
__device__ __align__(16) float g_Bd[SD*IDIM];
__device__ __align__(16) float g_Apow[64*SD*SD];          // A_d^{j+1}, j=0..63
__device__ __align__(16) float g_H[NBATCH*SEQLEN*SD];
__device__ __align__(16) float g_hprev[NBATCH*NCH*SD];

// ---------------- K0: discretization + A powers (1 block, 256 threads) ----------------
__global__ void k0_setup(const float* __restrict__ ll, const float* __restrict__ p,
                         const float* __restrict__ q,  const float* __restrict__ B,
                         const float* __restrict__ P) {
    __shared__ float core[SD*SD], tmp[SD*SD], Ac[SD*SD];
    __shared__ float aug[SD][96];
    __shared__ float fvec[SD];
    __shared__ float Sp[2][SD*SD];
    __shared__ int   pivs;
    int t = threadIdx.x;

    if (t < SD*SD) {
        int i = t >> 4, j = t & 15;
        float v = p[i] * q[j];
        if (i == j) v -= expf(ll[i]);
        core[t] = v;
    }
    __syncthreads();
    if (t < SD*SD) {
        int i = t >> 4, j = t & 15;
        float s = 0.f;
        for (int k = 0; k < SD; k++) s += P[i*SD+k] * core[k*SD+j];
        tmp[t] = s;
    }
    __syncthreads();
    if (t < SD*SD) {
        int i = t >> 4, j = t & 15;
        float s = 0.f;
        for (int k = 0; k < SD; k++) s += tmp[i*SD+k] * P[j*SD+k];
        Ac[t] = s;
    }
    __syncthreads();
    for (int f = t; f < SD*96; f += 256) {
        int r = f / 96, c = f % 96;
        float v;
        if (c < 16)      v = (r == c      ? 1.f : 0.f) - 0.5f*DTVAL*Ac[r*SD+c];
        else if (c < 32) v = (r == (c-16) ? 1.f : 0.f) + 0.5f*DTVAL*Ac[r*SD+(c-16)];
        else             v = DTVAL * B[r*IDIM + (c-32)];
        aug[r][c] = v;
    }
    __syncthreads();
    for (int col = 0; col < SD; col++) {
        if (t == 0) {
            int best = col; float bv = fabsf(aug[col][col]);
            for (int r = col+1; r < SD; r++) {
                float v = fabsf(aug[r][col]);
                if (v > bv) { bv = v; best = r; }
            }
            pivs = best;
        }
        __syncthreads();
        int pr = pivs;
        if (pr != col && t < 96) { float a = aug[col][t]; aug[col][t] = aug[pr][t]; aug[pr][t] = a; }
        __syncthreads();
        float pv = aug[col][col];
        if (t < SD) fvec[t] = aug[t][col];
        __syncthreads();
        if (t < 96) aug[col][t] *= (1.f / pv);
        __syncthreads();
        for (int f = t; f < SD*96; f += 256) {
            int r = f / 96, c = f % 96;
            if (r != col) aug[r][c] = fmaf(-fvec[r], aug[col][c], aug[r][c]);
        }
        __syncthreads();
    }
    if (t < SD*SD) { int r = t >> 4, c = t & 15; float v = aug[r][16+c]; g_Ad[t] = v; core[t] = v; Sp[0][t] = v; }
    for (int f = t; f < SD*IDIM; f += 256) { int r = f / IDIM, c = f % IDIM; g_Bd[f] = aug[r][32+c]; }
    __syncthreads();
    int cur = 0;
    for (int j = 0; j < 64; j++) {
        if (t < SD*SD) {
            g_Apow[j*256 + t] = Sp[cur][t];
            if (j == 63) g_AdL[t] = Sp[cur][t];
            if (j < 63) {
                int i = t >> 4, jj = t & 15;
                float s = 0.f;
                for (int k = 0; k < SD; k++) s += Sp[cur][i*SD+k] * core[k*SD+jj];
                Sp[cur^1][t] = s;
            }
        }
        __syncthreads();
        cur ^= 1;
    }
}

// ---------------- K1: local chunk scan (warp per (batch, chunk)) ----------------
__global__ void __launch_bounds__(256) k1_local(const float* __restrict__ x) {
    __shared__ __align__(16) float xs[8][16*64];
    __shared__ __align__(16) float hs[8][16*16];
    int warp = threadIdx.x >> 5, lane = threadIdx.x & 31;
    int wid = blockIdx.x * 8 + warp;
    int b = wid >> 7, c = wid & (NCH - 1);
    int n = lane & 15, half = lane >> 4;

    float Breg[32], Areg[16];
    {
        const float4* bp = (const float4*)(g_Bd + n*IDIM + half*32);
#pragma unroll
        for (int i = 0; i < 8; i++) { float4 v = bp[i]; Breg[4*i]=v.x; Breg[4*i+1]=v.y; Breg[4*i+2]=v.z; Breg[4*i+3]=v.w; }
        const float4* ap = (const float4*)(g_Ad + n*SD);
#pragma unroll
        for (int i = 0; i < 4; i++) { float4 v = ap[i]; Areg[4*i]=v.x; Areg[4*i+1]=v.y; Areg[4*i+2]=v.z; Areg[4*i+3]=v.w; }
    }
    const float4* gx = (const float4*)(x + ((size_t)b*SEQLEN + (size_t)c*LCH)*IDIM);
    float* gH = g_H + ((size_t)b*SEQLEN + (size_t)c*LCH)*SD;
    float* xw = xs[warp];
    float* hw = hs[warp];
    float h = 0.f;

    for (int tile = 0; tile < LCH/16; tile++) {
#pragma unroll
        for (int i = 0; i < 8; i++)
            ((float4*)xw)[lane + 32*i] = gx[tile*256 + lane + 32*i];
        __syncwarp();
#pragma unroll
        for (int tt = 0; tt < 16; tt++) {
            const float* xp = xw + tt*64 + half*32;
            float ua0=0.f, ua1=0.f, ua2=0.f, ua3=0.f;
#pragma unroll
            for (int k4 = 0; k4 < 8; k4++) {
                float4 v = *(const float4*)(xp + 4*k4);
                ua0 = fmaf(Breg[4*k4+0], v.x, ua0);
                ua1 = fmaf(Breg[4*k4+1], v.y, ua1);
                ua2 = fmaf(Breg[4*k4+2], v.z, ua2);
                ua3 = fmaf(Breg[4*k4+3], v.w, ua3);
            }
            float u = (ua0 + ua1) + (ua2 + ua3);
            u += __shfl_xor_sync(FULLMASK, u, 16);
            float h0 = u, h1 = 0.f;
#pragma unroll
            for (int m = 0; m < 16; m += 2) {
                h0 = fmaf(Areg[m],   __shfl_sync(FULLMASK, h, m),   h0);
                h1 = fmaf(Areg[m+1], __shfl_sync(FULLMASK, h, m+1), h1);
            }
            h = h0 + h1;
            if (half == 0) hw[tt*16 + n] = h;
        }
        __syncwarp();
        ((float4*)gH)[tile*64 + lane]      = ((float4*)hw)[lane];
        ((float4*)gH)[tile*64 + 32 + lane] = ((float4*)hw)[lane + 32];
        __syncwarp();
    }
}

// ---------------- K2: boundary scan across chunks (warp per batch) ----------------
__global__ void k2_scan() {
    __shared__ float ss[NCH*SD];
    int b = blockIdx.x;
    int lane = threadIdx.x;
    int n = lane & 15;
    for (int f = lane; f < NCH*SD; f += 32) {
        int c = f >> 4, nn = f & 15;
        ss[f] = g_H[((size_t)b*SEQLEN + (size_t)c*LCH + (LCH-1))*SD + nn];
    }
    __syncwarp();
    float AL[16];
    {
        const float4* ap = (const float4*)(g_AdL + n*SD);
#pragma unroll
        for (int i = 0; i < 4; i++) { float4 v = ap[i]; AL[4*i]=v.x; AL[4*i+1]=v.y; AL[4*i+2]=v.z; AL[4*i+3]=v.w; }
    }
    float h = 0.f;
    for (int c = 0; c < NCH; c++) {
        if (lane < 16) g_hprev[((size_t)b*NCH + c)*SD + n] = h;
        float h0 = ss[c*SD + n], h1 = 0.f;
#pragma unroll
        for (int m = 0; m < 16; m += 2) {
            h0 = fmaf(AL[m],   __shfl_sync(FULLMASK, h, m),   h0);
            h1 = fmaf(AL[m+1], __shfl_sync(FULLMASK, h, m+1), h1);
        }
        h = h0 + h1;
    }
}

// ---------------- K2.5b: parallel correction h_j += A^{j+1} h_prev ----------------
__global__ void __launch_bounds__(256) k25b() {
    __shared__ float shp[256];               // 16 chunks x 16 states
    int t = threadIdx.x;
    int j = t >> 2, n4 = (t & 3) << 2;

    float4 apr[16];                           // rows n4..n4+3 of A^{j+1}
#pragma unroll
    for (int i = 0; i < 4; i++)
#pragma unroll
        for (int w = 0; w < 4; w++)
            apr[i*4+w] = *(const float4*)(g_Apow + j*256 + (n4+i)*16 + w*4);

    int cid0 = blockIdx.x * 16;
    shp[t] = g_hprev[cid0*16 + t];
    __syncthreads();

    for (int ch = 0; ch < 16; ch++) {
        const float* hp = shp + ch*16;
        float z[4];
#pragma unroll
        for (int i = 0; i < 4; i++) {
            float s = 0.f;
#pragma unroll
            for (int w = 0; w < 4; w++) {
                float4 a = apr[i*4+w];
                s = fmaf(a.x, hp[w*4+0], s);
                s = fmaf(a.y, hp[w*4+1], s);
                s = fmaf(a.z, hp[w*4+2], s);
                s = fmaf(a.w, hp[w*4+3], s);
            }
            z[i] = s;
        }
        float* dst = g_H + (size_t)(cid0 + ch)*(LCH*SD) + t*4;
        float4 v = *(float4*)dst;
        v.x += z[0]; v.y += z[1]; v.z += z[2]; v.w += z[3];
        *(float4*)dst = v;
    }
}

// ---------------- K3: Y = [X|H] @ [D|C]^T with packed f32x2 FMA ----------------
#define WSTR 82
__global__ void __launch_bounds__(256, 2) k3_out(const float* __restrict__ x,
                                                 const float* __restrict__ C,
                                                 const float* __restrict__ D,
                                                 float* __restrict__ y) {
    __shared__ __align__(16) float Zs[128*40];     // 20.5 KB
    __shared__ __align__(16) float Ws[64*WSTR];    // 21.0 KB
    int tid = threadIdx.x;
    size_t row0 = (size_t)blockIdx.x * 128;
    int tr = tid >> 4, tc = tid & 15;

    // Ws[o][0..63] = D row o ; Ws[o][64..79] = C row o  (float2 stores: WSTR=82 keeps 8B alignment)
#pragma unroll
    for (int i = 0; i < 8; i++) {
        int f = tid + 256*i;                 // 2048 float2 = 64x64 D
        int o = f >> 5, k0 = (f & 31) << 1;
        float2 v = *(const float2*)(D + o*64 + k0);
        *(float2*)&Ws[o*WSTR + k0] = v;
    }
#pragma unroll
    for (int i = 0; i < 2; i++) {
        int f = tid + 256*i;                 // 512 float2 = 64x16 C
        int o = f >> 3, k0 = (f & 7) << 1;
        float2 v = *(const float2*)(C + o*16 + k0);
        *(float2*)&Ws[o*WSTR + 64 + k0] = v;
    }

    unsigned long long acc[8][4];
#pragma unroll
    for (int m = 0; m < 8; m++)
#pragma unroll
        for (int c = 0; c < 4; c++) acc[m][c] = 0ull;

    const float* za = Zs + (tr*8)*40;

#pragma unroll 1
    for (int h = 0; h < 2; h++) {
        if (h == 0) {
#pragma unroll
            for (int i = 0; i < 5; i++) {
                int f = tid + 256*i;                 // 1280 float4: k 0..39
                int r = f / 10, qq = f % 10;
                float4 v = *(const float4*)(x + (row0 + r)*64 + qq*4);
                *(float4*)&Zs[r*40 + qq*4] = v;
            }
        } else {
#pragma unroll
            for (int i = 0; i < 3; i++) {
                int f = tid + 256*i;                 // 768 float4: x k 40..63
                if (f < 768) {
                    int r = f / 6, qq = f % 6;
                    float4 v = *(const float4*)(x + (row0 + r)*64 + 40 + qq*4);
                    *(float4*)&Zs[r*40 + qq*4] = v;
                }
            }
#pragma unroll
            for (int i = 0; i < 2; i++) {
                int f = tid + 256*i;                 // 512 float4: H (k 64..79)
                int r = f >> 2, qq = f & 3;
                float4 v = *(const float4*)(g_H + (row0 + r)*16 + qq*4);
                *(float4*)&Zs[r*40 + 24 + qq*4] = v;
            }
        }
        __syncthreads();
        int kb = h * 40;
#pragma unroll
        for (int kp = 0; kp < 20; kp++) {
            unsigned long long a2[8], b2[4];
#pragma unroll
            for (int m = 0; m < 8; m++)
                a2[m] = *(const unsigned long long*)(za + m*40 + 2*kp);
#pragma unroll
            for (int c = 0; c < 4; c++)
                b2[c] = *(const unsigned long long*)(Ws + (tc + 16*c)*WSTR + kb + 2*kp);
#pragma unroll
            for (int m = 0; m < 8; m++)
#pragma unroll
                for (int c = 0; c < 4; c++)
                    asm("fma.rn.f32x2 %0, %1, %2, %0;"
                        : "+l"(acc[m][c]) : "l"(a2[m]), "l"(b2[c]));
        }
        __syncthreads();
    }

#pragma unroll
    for (int m = 0; m < 8; m++) {
        size_t row = row0 + tr*8 + m;
#pragma unroll
        for (int c = 0; c < 4; c++) {
            float lo, hi;
            asm("mov.b64 {%0,%1}, %2;" : "=f"(lo), "=f"(hi) : "l"(acc[m][c]));
            y[row*64 + tc + 16*c] = lo + hi;
        }
    }
}

extern "C" void kernel_launch(void* const* d_in, const int* in_sizes, int n_in,
                              void* d_out, int out_size) {
    const float* x  = (const float*)d_in[0];
    const float* ll = (const float*)d_in[1];
    const float* p  = (const float*)d_in[2];
    const float* q  = (const float*)d_in[3];
    const float* B  = (const float*)d_in[4];
    const float* C  = (const float*)d_in[5];
    const float* D  = (const float*)d_in[6];
    const float* P  = (const float*)d_in[7];
    float* y = (float*)d_out;

    k0_setup<<<1, 256>>>(ll, p, q, B, P);
    k1_local<<<(NBATCH*NCH)/8, 256>>>(x);
    k2_scan<<<NBATCH, 32>>>();
    k25b<<<(NBATCH*NCH)/16, 256>>>();
    k3_out<<<(NBATCH*SEQLEN)/128, 256>>>(x, C, D, y);
}

// round 5
// speedup vs baseline: 1.2898x; 1.0149x over previous
#include <cuda_runtime.h>
#include <math.h>

#define SD     16
#define IDIM   64
#define ODIM   64
#define NBATCH 32
#define SEQLEN 8192
#define LCH    64
#define NCH    (SEQLEN/LCH)
#define DTVAL  1.0f
#define FULLMASK 0xffffffffu

__device__ __align__(16) float g_Ad[SD*SD];
__device__ __align__(16) float g_AdL[SD*SD];
__device__ __align__(16) float g_Bd[SD*IDIM];
__device__ __align__(16) float g_Apow[64*SD*SD];          // A_d^{j+1}, j=0..63
__device__ __align__(16) float g_H[NBATCH*SEQLEN*SD];
__device__ __align__(16) float g_hprev[NBATCH*NCH*SD];

// ---------------- K0: discretization + A powers by doubling (1 block, 256 thr) ----------------
__global__ void k0_setup(const float* __restrict__ ll, const float* __restrict__ p,
                         const float* __restrict__ q,  const float* __restrict__ B,
                         const float* __restrict__ P) {
    __shared__ float core[SD*SD], tmp[SD*SD], Ac[SD*SD];
    __shared__ float aug[SD][96];
    __shared__ float fvec[SD];
    __shared__ int   pivs;
    int t = threadIdx.x;

    if (t < SD*SD) {
        int i = t >> 4, j = t & 15;
        float v = p[i] * q[j];
        if (i == j) v -= expf(ll[i]);
        core[t] = v;
    }
    __syncthreads();
    if (t < SD*SD) {
        int i = t >> 4, j = t & 15;
        float s = 0.f;
        for (int k = 0; k < SD; k++) s += P[i*SD+k] * core[k*SD+j];
        tmp[t] = s;
    }
    __syncthreads();
    if (t < SD*SD) {
        int i = t >> 4, j = t & 15;
        float s = 0.f;
        for (int k = 0; k < SD; k++) s += tmp[i*SD+k] * P[j*SD+k];
        Ac[t] = s;
    }
    __syncthreads();
    for (int f = t; f < SD*96; f += 256) {
        int r = f / 96, c = f % 96;
        float v;
        if (c < 16)      v = (r == c      ? 1.f : 0.f) - 0.5f*DTVAL*Ac[r*SD+c];
        else if (c < 32) v = (r == (c-16) ? 1.f : 0.f) + 0.5f*DTVAL*Ac[r*SD+(c-16)];
        else             v = DTVAL * B[r*IDIM + (c-32)];
        aug[r][c] = v;
    }
    __syncthreads();
    for (int col = 0; col < SD; col++) {
        if (t == 0) {
            int best = col; float bv = fabsf(aug[col][col]);
            for (int r = col+1; r < SD; r++) {
                float v = fabsf(aug[r][col]);
                if (v > bv) { bv = v; best = r; }
            }
            pivs = best;
        }
        __syncthreads();
        int pr = pivs;
        if (pr != col && t < 96) { float a = aug[col][t]; aug[col][t] = aug[pr][t]; aug[pr][t] = a; }
        __syncthreads();
        float pv = aug[col][col];
        if (t < SD) fvec[t] = aug[t][col];
        __syncthreads();
        if (t < 96) aug[col][t] *= (1.f / pv);
        __syncthreads();
        for (int f = t; f < SD*96; f += 256) {
            int r = f / 96, c = f % 96;
            if (r != col) aug[r][c] = fmaf(-fvec[r], aug[col][c], aug[r][c]);
        }
        __syncthreads();
    }
    if (t < SD*SD) { int r = t >> 4, c = t & 15; float v = aug[r][16+c]; g_Ad[t] = v; g_Apow[t] = v; }
    for (int f = t; f < SD*IDIM; f += 256) { int r = f / IDIM, c = f % IDIM; g_Bd[f] = aug[r][32+c]; }
    __syncthreads();
    // powers by doubling: have A^1..A^m, build A^{m+1}..A^{2m} = A^{i+1} @ A^m
    for (int m = 1; m <= 32; m <<= 1) {
        for (int f = t; f < m*256; f += 256) {
            int i = f >> 8, e = f & 255, r = e >> 4, c2 = e & 15;
            const float* L = g_Apow + i*256 + r*16;
            const float* R = g_Apow + (m-1)*256;
            float s = 0.f;
#pragma unroll
            for (int k = 0; k < 16; k++) s = fmaf(L[k], R[k*16 + c2], s);
            g_Apow[(m+i)*256 + e] = s;
        }
        __syncthreads();
    }
    if (t < SD*SD) g_AdL[t] = g_Apow[63*256 + t];
}

// ---------------- K1: local chunk scan (warp per (batch, chunk)) ----------------
__global__ void __launch_bounds__(256) k1_local(const float* __restrict__ x) {
    __shared__ __align__(16) float xs[8][16*64];
    __shared__ __align__(16) float hs[8][16*16];
    int warp = threadIdx.x >> 5, lane = threadIdx.x & 31;
    int wid = blockIdx.x * 8 + warp;
    int b = wid >> 7, c = wid & (NCH - 1);
    int n = lane & 15, half = lane >> 4;
    int mb = half * 8;

    float Breg[32], Areg[8];
    {
        const float4* bp = (const float4*)(g_Bd + n*IDIM + half*32);
#pragma unroll
        for (int i = 0; i < 8; i++) { float4 v = bp[i]; Breg[4*i]=v.x; Breg[4*i+1]=v.y; Breg[4*i+2]=v.z; Breg[4*i+3]=v.w; }
        const float4* ap = (const float4*)(g_Ad + n*SD + mb);   // this half's 8 columns
#pragma unroll
        for (int i = 0; i < 2; i++) { float4 v = ap[i]; Areg[4*i]=v.x; Areg[4*i+1]=v.y; Areg[4*i+2]=v.z; Areg[4*i+3]=v.w; }
    }
    const float4* gx = (const float4*)(x + ((size_t)b*SEQLEN + (size_t)c*LCH)*IDIM);
    float* gH = g_H + ((size_t)b*SEQLEN + (size_t)c*LCH)*SD;
    float* xw = xs[warp];
    float* hw = hs[warp];
    float h = 0.f;                         // full h, maintained on all lanes

    for (int tile = 0; tile < LCH/16; tile++) {
#pragma unroll
        for (int i = 0; i < 8; i++)
            ((float4*)xw)[lane + 32*i] = gx[tile*256 + lane + 32*i];
        __syncwarp();
#pragma unroll
        for (int tt = 0; tt < 16; tt++) {
            const float* xp = xw + tt*64 + half*32;
            float a0=0.f, a1=0.f, a2=0.f, a3=0.f;
#pragma unroll
            for (int k4 = 0; k4 < 8; k4++) {
                float4 v = *(const float4*)(xp + 4*k4);
                a0 = fmaf(Breg[4*k4+0], v.x, a0);
                a1 = fmaf(Breg[4*k4+1], v.y, a1);
                a2 = fmaf(Breg[4*k4+2], v.z, a2);
                a3 = fmaf(Breg[4*k4+3], v.w, a3);
            }
            float acc0 = a0 + a2, acc1 = a1 + a3;  // this half's u partial
#pragma unroll
            for (int i = 0; i < 8; i += 2) {       // this half's A·h partial (m = mb..mb+7)
                acc0 = fmaf(Areg[i],   __shfl_sync(FULLMASK, h, mb + i),     acc0);
                acc1 = fmaf(Areg[i+1], __shfl_sync(FULLMASK, h, mb + i + 1), acc1);
            }
            float hp = acc0 + acc1;
            h = hp + __shfl_xor_sync(FULLMASK, hp, 16);   // combine halves -> full h
            if (half == 0) hw[tt*16 + n] = h;
        }
        __syncwarp();
        ((float4*)gH)[tile*64 + lane]      = ((float4*)hw)[lane];
        ((float4*)gH)[tile*64 + 32 + lane] = ((float4*)hw)[lane + 32];
        __syncwarp();
    }
}

// ---------------- K2: boundary scan across chunks (warp per batch) ----------------
__global__ void k2_scan() {
    __shared__ float ss[NCH*SD];
    int b = blockIdx.x;
    int lane = threadIdx.x;
    int n = lane & 15;
    for (int f = lane; f < NCH*SD; f += 32) {
        int c = f >> 4, nn = f & 15;
        ss[f] = g_H[((size_t)b*SEQLEN + (size_t)c*LCH + (LCH-1))*SD + nn];
    }
    __syncwarp();
    float AL[16];
    {
        const float4* ap = (const float4*)(g_AdL + n*SD);
#pragma unroll
        for (int i = 0; i < 4; i++) { float4 v = ap[i]; AL[4*i]=v.x; AL[4*i+1]=v.y; AL[4*i+2]=v.z; AL[4*i+3]=v.w; }
    }
    float h = 0.f;
    for (int c = 0; c < NCH; c++) {
        if (lane < 16) g_hprev[((size_t)b*NCH + c)*SD + n] = h;
        float h0 = ss[c*SD + n], h1 = 0.f;
#pragma unroll
        for (int m = 0; m < 16; m += 2) {
            h0 = fmaf(AL[m],   __shfl_sync(FULLMASK, h, m),   h0);
            h1 = fmaf(AL[m+1], __shfl_sync(FULLMASK, h, m+1), h1);
        }
        h = h0 + h1;
    }
}

// ---------------- K2.5b: parallel correction h_j += A^{j+1} h_prev (4 chunks/block) ----------------
__global__ void __launch_bounds__(256) k25b() {
    __shared__ float shp[64];                 // 4 chunks x 16 states
    int t = threadIdx.x;
    int j = t >> 2, n4 = (t & 3) << 2;

    float4 apr[16];                           // rows n4..n4+3 of A^{j+1}
#pragma unroll
    for (int i = 0; i < 4; i++)
#pragma unroll
        for (int w = 0; w < 4; w++)
            apr[i*4+w] = *(const float4*)(g_Apow + j*256 + (n4+i)*16 + w*4);

    int cid0 = blockIdx.x * 4;
    if (t < 64) shp[t] = g_hprev[cid0*16 + t];
    __syncthreads();

#pragma unroll
    for (int ch = 0; ch < 4; ch++) {
        const float* hp = shp + ch*16;
        float z[4];
#pragma unroll
        for (int i = 0; i < 4; i++) {
            float s = 0.f;
#pragma unroll
            for (int w = 0; w < 4; w++) {
                float4 a = apr[i*4+w];
                s = fmaf(a.x, hp[w*4+0], s);
                s = fmaf(a.y, hp[w*4+1], s);
                s = fmaf(a.z, hp[w*4+2], s);
                s = fmaf(a.w, hp[w*4+3], s);
            }
            z[i] = s;
        }
        float* dst = g_H + (size_t)(cid0 + ch)*(LCH*SD) + t*4;
        float4 v = *(float4*)dst;
        v.x += z[0]; v.y += z[1]; v.z += z[2]; v.w += z[3];
        *(float4*)dst = v;
    }
}

// ---------------- K3: Y = [X|H] @ [D|C]^T with packed f32x2 FMA ----------------
#define WSTR 82
__global__ void __launch_bounds__(256, 2) k3_out(const float* __restrict__ x,
                                                 const float* __restrict__ C,
                                                 const float* __restrict__ D,
                                                 float* __restrict__ y) {
    __shared__ __align__(16) float Zs[128*40];
    __shared__ __align__(16) float Ws[64*WSTR];
    int tid = threadIdx.x;
    size_t row0 = (size_t)blockIdx.x * 128;
    int tr = tid >> 4, tc = tid & 15;

#pragma unroll
    for (int i = 0; i < 8; i++) {
        int f = tid + 256*i;
        int o = f >> 5, k0 = (f & 31) << 1;
        float2 v = *(const float2*)(D + o*64 + k0);
        *(float2*)&Ws[o*WSTR + k0] = v;
    }
#pragma unroll
    for (int i = 0; i < 2; i++) {
        int f = tid + 256*i;
        int o = f >> 3, k0 = (f & 7) << 1;
        float2 v = *(const float2*)(C + o*16 + k0);
        *(float2*)&Ws[o*WSTR + 64 + k0] = v;
    }

    unsigned long long acc[8][4];
#pragma unroll
    for (int m = 0; m < 8; m++)
#pragma unroll
        for (int c = 0; c < 4; c++) acc[m][c] = 0ull;

    const float* za = Zs + (tr*8)*40;

#pragma unroll 1
    for (int h = 0; h < 2; h++) {
        if (h == 0) {
#pragma unroll
            for (int i = 0; i < 5; i++) {
                int f = tid + 256*i;
                int r = f / 10, qq = f % 10;
                float4 v = *(const float4*)(x + (row0 + r)*64 + qq*4);
                *(float4*)&Zs[r*40 + qq*4] = v;
            }
        } else {
#pragma unroll
            for (int i = 0; i < 3; i++) {
                int f = tid + 256*i;
                if (f < 768) {
                    int r = f / 6, qq = f % 6;
                    float4 v = *(const float4*)(x + (row0 + r)*64 + 40 + qq*4);
                    *(float4*)&Zs[r*40 + qq*4] = v;
                }
            }
#pragma unroll
            for (int i = 0; i < 2; i++) {
                int f = tid + 256*i;
                int r = f >> 2, qq = f & 3;
                float4 v = *(const float4*)(g_H + (row0 + r)*16 + qq*4);
                *(float4*)&Zs[r*40 + 24 + qq*4] = v;
            }
        }
        __syncthreads();
        int kb = h * 40;
#pragma unroll
        for (int kp = 0; kp < 20; kp++) {
            unsigned long long a2[8], b2[4];
#pragma unroll
            for (int m = 0; m < 8; m++)
                a2[m] = *(const unsigned long long*)(za + m*40 + 2*kp);
#pragma unroll
            for (int c = 0; c < 4; c++)
                b2[c] = *(const unsigned long long*)(Ws + (tc + 16*c)*WSTR + kb + 2*kp);
#pragma unroll
            for (int m = 0; m < 8; m++)
#pragma unroll
                for (int c = 0; c < 4; c++)
                    asm("fma.rn.f32x2 %0, %1, %2, %0;"
                        : "+l"(acc[m][c]) : "l"(a2[m]), "l"(b2[c]));
        }
        __syncthreads();
    }

#pragma unroll
    for (int m = 0; m < 8; m++) {
        size_t row = row0 + tr*8 + m;
#pragma unroll
        for (int c = 0; c < 4; c++) {
            float lo, hi;
            asm("mov.b64 {%0,%1}, %2;" : "=f"(lo), "=f"(hi) : "l"(acc[m][c]));
            y[row*64 + tc + 16*c] = lo + hi;
        }
    }
}

extern "C" void kernel_launch(void* const* d_in, const int* in_sizes, int n_in,
                              void* d_out, int out_size) {
    const float* x  = (const float*)d_in[0];
    const float* ll = (const float*)d_in[1];
    const float* p  = (const float*)d_in[2];
    const float* q  = (const float*)d_in[3];
    const float* B  = (const float*)d_in[4];
    const float* C  = (const float*)d_in[5];
    const float* D  = (const float*)d_in[6];
    const float* P  = (const float*)d_in[7];
    float* y = (float*)d_out;

    k0_setup<<<1, 256>>>(ll, p, q, B, P);
    k1_local<<<(NBATCH*NCH)/8, 256>>>(x);
    k2_scan<<<NBATCH, 32>>>();
    k25b<<<(NBATCH*NCH)/4, 256>>>();
    k3_out<<<(NBATCH*SEQLEN)/128, 256>>>(x, C, D, y);
}

// round 6
// speedup vs baseline: 1.3622x; 1.0561x over previous
#include <cuda_runtime.h>
#include <math.h>

#define SD     16
#define IDIM   64
#define ODIM   64
#define NBATCH 32
#define SEQLEN 8192
#define LCH    64
#define NCH    (SEQLEN/LCH)
#define DTVAL  1.0f
#define FULLMASK 0xffffffffu

__device__ __align__(16) float g_Ad[SD*SD];
__device__ __align__(16) float g_AdL[SD*SD];
__device__ __align__(16) float g_Bd[SD*IDIM];
__device__ __align__(16) float g_Apow[64*SD*SD];          // A_d^{j+1}, j=0..63
__device__ __align__(16) float g_H[NBATCH*SEQLEN*SD];
__device__ __align__(16) float g_hprev[NBATCH*NCH*SD];

// ---------------- K0: discretization + A powers by doubling (1 block, 256 thr) ----------------
__global__ void k0_setup(const float* __restrict__ ll, const float* __restrict__ p,
                         const float* __restrict__ q,  const float* __restrict__ B,
                         const float* __restrict__ P) {
    __shared__ float core[SD*SD], tmp[SD*SD], Ac[SD*SD];
    __shared__ float aug[SD][96];
    __shared__ float fvec[SD];
    __shared__ int   pivs;
    int t = threadIdx.x;

    if (t < SD*SD) {
        int i = t >> 4, j = t & 15;
        float v = p[i] * q[j];
        if (i == j) v -= expf(ll[i]);
        core[t] = v;
    }
    __syncthreads();
    if (t < SD*SD) {
        int i = t >> 4, j = t & 15;
        float s = 0.f;
        for (int k = 0; k < SD; k++) s += P[i*SD+k] * core[k*SD+j];
        tmp[t] = s;
    }
    __syncthreads();
    if (t < SD*SD) {
        int i = t >> 4, j = t & 15;
        float s = 0.f;
        for (int k = 0; k < SD; k++) s += tmp[i*SD+k] * P[j*SD+k];
        Ac[t] = s;
    }
    __syncthreads();
    for (int f = t; f < SD*96; f += 256) {
        int r = f / 96, c = f % 96;
        float v;
        if (c < 16)      v = (r == c      ? 1.f : 0.f) - 0.5f*DTVAL*Ac[r*SD+c];
        else if (c < 32) v = (r == (c-16) ? 1.f : 0.f) + 0.5f*DTVAL*Ac[r*SD+(c-16)];
        else             v = DTVAL * B[r*IDIM + (c-32)];
        aug[r][c] = v;
    }
    __syncthreads();
    for (int col = 0; col < SD; col++) {
        if (t == 0) {
            int best = col; float bv = fabsf(aug[col][col]);
            for (int r = col+1; r < SD; r++) {
                float v = fabsf(aug[r][col]);
                if (v > bv) { bv = v; best = r; }
            }
            pivs = best;
        }
        __syncthreads();
        int pr = pivs;
        if (pr != col && t < 96) { float a = aug[col][t]; aug[col][t] = aug[pr][t]; aug[pr][t] = a; }
        __syncthreads();
        float pv = aug[col][col];
        if (t < SD) fvec[t] = aug[t][col];
        __syncthreads();
        if (t < 96) aug[col][t] *= (1.f / pv);
        __syncthreads();
        for (int f = t; f < SD*96; f += 256) {
            int r = f / 96, c = f % 96;
            if (r != col) aug[r][c] = fmaf(-fvec[r], aug[col][c], aug[r][c]);
        }
        __syncthreads();
    }
    if (t < SD*SD) { int r = t >> 4, c = t & 15; float v = aug[r][16+c]; g_Ad[t] = v; g_Apow[t] = v; }
    for (int f = t; f < SD*IDIM; f += 256) { int r = f / IDIM, c = f % IDIM; g_Bd[f] = aug[r][32+c]; }
    __syncthreads();
    // powers by doubling: have A^1..A^m, build A^{m+1}..A^{2m} = A^{i+1} @ A^m
    for (int m = 1; m <= 32; m <<= 1) {
        for (int f = t; f < m*256; f += 256) {
            int i = f >> 8, e = f & 255, r = e >> 4, c2 = e & 15;
            const float* L = g_Apow + i*256 + r*16;
            const float* R = g_Apow + (m-1)*256;
            float s = 0.f;
#pragma unroll
            for (int k = 0; k < 16; k++) s = fmaf(L[k], R[k*16 + c2], s);
            g_Apow[(m+i)*256 + e] = s;
        }
        __syncthreads();
    }
    if (t < SD*SD) g_AdL[t] = g_Apow[63*256 + t];
}

// ---------------- K1: local chunk scan (warp per (batch, chunk)) ----------------
__global__ void __launch_bounds__(256) k1_local(const float* __restrict__ x) {
    __shared__ __align__(16) float xs[8][16*64];
    __shared__ __align__(16) float hs[8][16*16];
    int warp = threadIdx.x >> 5, lane = threadIdx.x & 31;
    int wid = blockIdx.x * 8 + warp;
    int b = wid >> 7, c = wid & (NCH - 1);
    int n = lane & 15, half = lane >> 4;
    int mb = half * 8;

    float Breg[32], Areg[8];
    {
        const float4* bp = (const float4*)(g_Bd + n*IDIM + half*32);
#pragma unroll
        for (int i = 0; i < 8; i++) { float4 v = bp[i]; Breg[4*i]=v.x; Breg[4*i+1]=v.y; Breg[4*i+2]=v.z; Breg[4*i+3]=v.w; }
        const float4* ap = (const float4*)(g_Ad + n*SD + mb);
#pragma unroll
        for (int i = 0; i < 2; i++) { float4 v = ap[i]; Areg[4*i]=v.x; Areg[4*i+1]=v.y; Areg[4*i+2]=v.z; Areg[4*i+3]=v.w; }
    }
    const float4* gx = (const float4*)(x + ((size_t)b*SEQLEN + (size_t)c*LCH)*IDIM);
    float* gH = g_H + ((size_t)b*SEQLEN + (size_t)c*LCH)*SD;
    float* xw = xs[warp];
    float* hw = hs[warp];
    float h = 0.f;

    for (int tile = 0; tile < LCH/16; tile++) {
#pragma unroll
        for (int i = 0; i < 8; i++)
            ((float4*)xw)[lane + 32*i] = gx[tile*256 + lane + 32*i];
        __syncwarp();
#pragma unroll
        for (int tt = 0; tt < 16; tt++) {
            const float* xp = xw + tt*64 + half*32;
            float a0=0.f, a1=0.f, a2=0.f, a3=0.f;
#pragma unroll
            for (int k4 = 0; k4 < 8; k4++) {
                float4 v = *(const float4*)(xp + 4*k4);
                a0 = fmaf(Breg[4*k4+0], v.x, a0);
                a1 = fmaf(Breg[4*k4+1], v.y, a1);
                a2 = fmaf(Breg[4*k4+2], v.z, a2);
                a3 = fmaf(Breg[4*k4+3], v.w, a3);
            }
            float acc0 = a0 + a2, acc1 = a1 + a3;
#pragma unroll
            for (int i = 0; i < 8; i += 2) {
                acc0 = fmaf(Areg[i],   __shfl_sync(FULLMASK, h, mb + i),     acc0);
                acc1 = fmaf(Areg[i+1], __shfl_sync(FULLMASK, h, mb + i + 1), acc1);
            }
            float hp = acc0 + acc1;
            h = hp + __shfl_xor_sync(FULLMASK, hp, 16);
            if (half == 0) hw[tt*16 + n] = h;
        }
        __syncwarp();
        ((float4*)gH)[tile*64 + lane]      = ((float4*)hw)[lane];
        ((float4*)gH)[tile*64 + 32 + lane] = ((float4*)hw)[lane + 32];
        __syncwarp();
    }
}

// ---------------- K2: boundary scan across chunks (warp per batch) ----------------
__global__ void k2_scan() {
    __shared__ float ss[NCH*SD];
    int b = blockIdx.x;
    int lane = threadIdx.x;
    int n = lane & 15;
    for (int f = lane; f < NCH*SD; f += 32) {
        int c = f >> 4, nn = f & 15;
        ss[f] = g_H[((size_t)b*SEQLEN + (size_t)c*LCH + (LCH-1))*SD + nn];
    }
    __syncwarp();
    float AL[16];
    {
        const float4* ap = (const float4*)(g_AdL + n*SD);
#pragma unroll
        for (int i = 0; i < 4; i++) { float4 v = ap[i]; AL[4*i]=v.x; AL[4*i+1]=v.y; AL[4*i+2]=v.z; AL[4*i+3]=v.w; }
    }
    float h = 0.f;
    for (int c = 0; c < NCH; c++) {
        if (lane < 16) g_hprev[((size_t)b*NCH + c)*SD + n] = h;
        float h0 = ss[c*SD + n], h1 = 0.f;
#pragma unroll
        for (int m = 0; m < 16; m += 2) {
            h0 = fmaf(AL[m],   __shfl_sync(FULLMASK, h, m),   h0);
            h1 = fmaf(AL[m+1], __shfl_sync(FULLMASK, h, m+1), h1);
        }
        h = h0 + h1;
    }
}

// ---------------- K2.5c: h_j += A^{j+1} h_prev, fully coalesced ----------------
// grid (512, 4): block = 8 chunks x (16 j-values, by*16..by*16+15), 256 threads,
// thread -> (jloc = t>>4, n = t&15): one output element, 16 FMAs per chunk.
#define K25_CHUNKS 8
#define PROW 17
__global__ void __launch_bounds__(256) k25c() {
    __shared__ float sA[16*16*PROW];            // 16 powers, padded rows: 17.4 KB
    __shared__ float shp[K25_CHUNKS*16];
    int t = threadIdx.x;
    int bx = blockIdx.x, by = blockIdx.y;
    int jloc = t >> 4, n = t & 15;

    // coalesced load of 16 powers into padded smem
#pragma unroll
    for (int i = 0; i < 16; i++) {
        int f = t + 256*i;                       // 0..4095
        int jl = f >> 8, e = f & 255, r = e >> 4, c = e & 15;
        sA[jl*(16*PROW) + r*PROW + c] = g_Apow[(by*16 + jl)*256 + e];
    }
    if (t < K25_CHUNKS*16) shp[t] = g_hprev[bx*K25_CHUNKS*16 + t];
    __syncthreads();

    float a[16];
    {
        const float* Ar = sA + jloc*(16*PROW) + n*PROW;   // row n of A^{by*16+jloc+1}
#pragma unroll
        for (int k = 0; k < 16; k++) a[k] = Ar[k];
    }
#pragma unroll
    for (int ch = 0; ch < K25_CHUNKS; ch++) {
        const float* hp = shp + ch*16;
        float s = 0.f;
#pragma unroll
        for (int k = 0; k < 16; k++) s = fmaf(a[k], hp[k], s);
        g_H[(size_t)(bx*K25_CHUNKS + ch)*(LCH*SD) + by*256 + t] += s;
    }
}

// ---------------- K3: Y = [X|H] @ [D|C]^T with packed f32x2 FMA ----------------
#define WSTR 82
__global__ void __launch_bounds__(256, 2) k3_out(const float* __restrict__ x,
                                                 const float* __restrict__ C,
                                                 const float* __restrict__ D,
                                                 float* __restrict__ y) {
    __shared__ __align__(16) float Zs[128*40];
    __shared__ __align__(16) float Ws[64*WSTR];
    int tid = threadIdx.x;
    size_t row0 = (size_t)blockIdx.x * 128;
    int tr = tid >> 4, tc = tid & 15;

#pragma unroll
    for (int i = 0; i < 8; i++) {
        int f = tid + 256*i;
        int o = f >> 5, k0 = (f & 31) << 1;
        float2 v = *(const float2*)(D + o*64 + k0);
        *(float2*)&Ws[o*WSTR + k0] = v;
    }
#pragma unroll
    for (int i = 0; i < 2; i++) {
        int f = tid + 256*i;
        int o = f >> 3, k0 = (f & 7) << 1;
        float2 v = *(const float2*)(C + o*16 + k0);
        *(float2*)&Ws[o*WSTR + 64 + k0] = v;
    }

    unsigned long long acc[8][4];
#pragma unroll
    for (int m = 0; m < 8; m++)
#pragma unroll
        for (int c = 0; c < 4; c++) acc[m][c] = 0ull;

    const float* za = Zs + (tr*8)*40;

#pragma unroll 1
    for (int h = 0; h < 2; h++) {
        if (h == 0) {
#pragma unroll
            for (int i = 0; i < 5; i++) {
                int f = tid + 256*i;
                int r = f / 10, qq = f % 10;
                float4 v = *(const float4*)(x + (row0 + r)*64 + qq*4);
                *(float4*)&Zs[r*40 + qq*4] = v;
            }
        } else {
#pragma unroll
            for (int i = 0; i < 3; i++) {
                int f = tid + 256*i;
                if (f < 768) {
                    int r = f / 6, qq = f % 6;
                    float4 v = *(const float4*)(x + (row0 + r)*64 + 40 + qq*4);
                    *(float4*)&Zs[r*40 + qq*4] = v;
                }
            }
#pragma unroll
            for (int i = 0; i < 2; i++) {
                int f = tid + 256*i;
                int r = f >> 2, qq = f & 3;
                float4 v = *(const float4*)(g_H + (row0 + r)*16 + qq*4);
                *(float4*)&Zs[r*40 + 24 + qq*4] = v;
            }
        }
        __syncthreads();
        int kb = h * 40;
#pragma unroll
        for (int kp = 0; kp < 20; kp++) {
            unsigned long long a2[8], b2[4];
#pragma unroll
            for (int m = 0; m < 8; m++)
                a2[m] = *(const unsigned long long*)(za + m*40 + 2*kp);
#pragma unroll
            for (int c = 0; c < 4; c++)
                b2[c] = *(const unsigned long long*)(Ws + (tc + 16*c)*WSTR + kb + 2*kp);
#pragma unroll
            for (int m = 0; m < 8; m++)
#pragma unroll
                for (int c = 0; c < 4; c++)
                    asm("fma.rn.f32x2 %0, %1, %2, %0;"
                        : "+l"(acc[m][c]) : "l"(a2[m]), "l"(b2[c]));
        }
        __syncthreads();
    }

#pragma unroll
    for (int m = 0; m < 8; m++) {
        size_t row = row0 + tr*8 + m;
#pragma unroll
        for (int c = 0; c < 4; c++) {
            float lo, hi;
            asm("mov.b64 {%0,%1}, %2;" : "=f"(lo), "=f"(hi) : "l"(acc[m][c]));
            y[row*64 + tc + 16*c] = lo + hi;
        }
    }
}

extern "C" void kernel_launch(void* const* d_in, const int* in_sizes, int n_in,
                              void* d_out, int out_size) {
    const float* x  = (const float*)d_in[0];
    const float* ll = (const float*)d_in[1];
    const float* p  = (const float*)d_in[2];
    const float* q  = (const float*)d_in[3];
    const float* B  = (const float*)d_in[4];
    const float* C  = (const float*)d_in[5];
    const float* D  = (const float*)d_in[6];
    const float* P  = (const float*)d_in[7];
    float* y = (float*)d_out;

    k0_setup<<<1, 256>>>(ll, p, q, B, P);
    k1_local<<<(NBATCH*NCH)/8, 256>>>(x);
    k2_scan<<<NBATCH, 32>>>();
    dim3 g25(NBATCH*NCH/K25_CHUNKS, 4);
    k25c<<<g25, 256>>>();
    k3_out<<<(NBATCH*SEQLEN)/128, 256>>>(x, C, D, y);
}